// round 6
// baseline (speedup 1.0000x reference)
#include <cuda_runtime.h>
#include <cuda_fp16.h>
#include <cstdint>

#define E_N 100000
#define R_N 64
#define I_N 256
#define O_N 256
#define TILE_M 128
#define N_TILES ((E_N + TILE_M - 1) / TILE_M)   // 782

#define WSUM_BLOCKS 1024
#define XSUM_BLOCKS ((E_N + 7) / 8)
#define FUSE_BLOCKS (WSUM_BLOCKS + XSUM_BLOCKS)

// Main-kernel dynamic smem (103428 B -> 2 CTAs/SM)
#define SM_CS0   0
#define SM_CS1   32768
#define SM_XS0   65536
#define SM_XS1   66048
#define SM_A     66560
#define A_BUF    18432
#define SM_NXT   (SM_A + 2 * A_BUF)       // 4B queue-broadcast slot
#define SM_TOT   (SM_NXT + 4)
#define A_STRIDE 144                      // %128==16 -> conflict-free LDSM

__device__ float g_wpart[16 * R_N * O_N];
__device__ float g_wsum[R_N * O_N];
__device__ float g_xsum[E_N];
__device__ int   g_tile_ctr;

// ---------------------------------------------------------------------------
// Kernel 1 (fused): blocks [0,1024) -> W partial sums; rest -> x row sums.
// ---------------------------------------------------------------------------
__global__ __launch_bounds__(256, 8)
void fused_stream_kernel(const float* __restrict__ W,
                         const float* __restrict__ x) {
    const int bid = blockIdx.x;
    if (bid < WSUM_BLOCKS) {
        const int r = bid & 63;
        const int part = bid >> 6;
        const int o = threadIdx.x;
        const float* base = W + ((size_t)(r * I_N + part * 16)) * O_N + o;
        float s = 0.f;
#pragma unroll
        for (int i = 0; i < 16; ++i) s += base[(size_t)i * O_N];
        g_wpart[(part * R_N + r) * O_N + o] = s;
    } else {
        const int warp = threadIdx.x >> 5, lane = threadIdx.x & 31;
        const int row = (bid - WSUM_BLOCKS) * 8 + warp;
        if (row >= E_N) return;
        const float4* xp = (const float4*)x + (size_t)row * 64;
        float4 v0 = xp[lane], v1 = xp[lane + 32];
        float s = (v0.x + v0.y) + (v0.z + v0.w) + (v1.x + v1.y) + (v1.z + v1.w);
#pragma unroll
        for (int d = 16; d; d >>= 1) s += __shfl_xor_sync(0xffffffffu, s, d);
        if (lane == 0) g_xsum[row] = s;
    }
}

// ---------------------------------------------------------------------------
// Kernel 2: collapse W partials -> g_wsum; reset the tile work-queue counter.
// ---------------------------------------------------------------------------
__global__ void wsum_final_kernel(int ctr_start) {
    const int r = blockIdx.x, o = threadIdx.x;
    float s = 0.f;
#pragma unroll
    for (int p = 0; p < 16; ++p) s += g_wpart[(p * R_N + r) * O_N + o];
    g_wsum[r * O_N + o] = s;
    if (r == 0 && o == 0) g_tile_ctr = ctr_start;
}

// ---------------------------------------------------------------------------
// helpers
// ---------------------------------------------------------------------------
static __device__ __forceinline__ void mma16816(float* acc, const uint32_t* a,
                                                uint32_t b0, uint32_t b1) {
    asm volatile(
        "mma.sync.aligned.m16n8k16.row.col.f32.f16.f16.f32 "
        "{%0,%1,%2,%3}, {%4,%5,%6,%7}, {%8,%9}, {%0,%1,%2,%3};"
        : "+f"(acc[0]), "+f"(acc[1]), "+f"(acc[2]), "+f"(acc[3])
        : "r"(a[0]), "r"(a[1]), "r"(a[2]), "r"(a[3]), "r"(b0), "r"(b1));
}
static __device__ __forceinline__ void ldsm4(uint32_t* r, uint32_t saddr) {
    asm volatile("ldmatrix.sync.aligned.m8n8.x4.shared.b16 {%0,%1,%2,%3}, [%4];"
                 : "=r"(r[0]), "=r"(r[1]), "=r"(r[2]), "=r"(r[3]) : "r"(saddr));
}
static __device__ __forceinline__ uint32_t pack2(__half a, __half b) {
    __half2 h; h.x = a; h.y = b;
    return *(uint32_t*)&h;
}
static __device__ __forceinline__ void split16(float v, __half& hi, __half& lo) {
    hi = __float2half_rn(v);
    lo = __float2half_rn(v - __half2float(hi));
}
// FMA-pipe reciprocal (no MUFU): magic seed + 2 Newton iterations
static __device__ __forceinline__ float frcp(float y) {
    float r = __uint_as_float(0x7EF311C3u - __float_as_uint(y));
    r = r * __fmaf_rn(-y, r, 2.0f);
    r = r * __fmaf_rn(-y, r, 2.0f);
    return r;
}
static __device__ __forceinline__ void cp16(uint32_t dst, const void* src,
                                            uint32_t sz) {
    asm volatile("cp.async.cg.shared.global [%0], [%1], 16, %2;"
                 :: "r"(dst), "l"(src), "r"(sz) : "memory");
}
static __device__ __forceinline__ void cp4(uint32_t dst, const void* src,
                                           uint32_t sz) {
    asm volatile("cp.async.ca.shared.global [%0], [%1], 4, %2;"
                 :: "r"(dst), "l"(src), "r"(sz) : "memory");
}

// ---------------------------------------------------------------------------
// Kernel 3: persistent main kernel, 2 CTAs/SM, dynamic tile queue.
// ---------------------------------------------------------------------------
__global__ __launch_bounds__(256, 2)
void rgcn_hmma_kernel(const float* __restrict__ cs,
                      float* __restrict__ out) {
    extern __shared__ __align__(16) char sm[];
    const uint32_t sbase = (uint32_t)__cvta_generic_to_shared(sm);
    const int t = threadIdx.x;
    const int warp = t >> 5, lane = t & 31;

    // ---- init: stage Wsum in smem (overlaps cs bufs), extract B frags -----
    float* s_w = (float*)sm;
#pragma unroll 4
    for (int i = 0; i < 64; ++i) {
        int idx = i * 256 + t;
        s_w[idx] = g_wsum[idx];
    }
    __syncthreads();

    uint32_t bh[4][4][2], bl[4][4][2];
    {
        const int n = warp * 32 + (lane >> 2);
#pragma unroll
        for (int nt = 0; nt < 4; ++nt)
#pragma unroll
            for (int ks = 0; ks < 4; ++ks) {
                int kb = ks * 16 + 2 * (lane & 3);
                int nn = n + nt * 8;
                float w00 = s_w[kb * 256 + nn];
                float w01 = s_w[(kb + 1) * 256 + nn];
                float w10 = s_w[(kb + 8) * 256 + nn];
                float w11 = s_w[(kb + 9) * 256 + nn];
                __half h00, l00, h01, l01, h10, l10, h11, l11;
                split16(w00, h00, l00); split16(w01, h01, l01);
                split16(w10, h10, l10); split16(w11, h11, l11);
                bh[nt][ks][0] = pack2(h00, h01); bh[nt][ks][1] = pack2(h10, h11);
                bl[nt][ks][0] = pack2(l00, l01); bl[nt][ks][1] = pack2(l10, l11);
            }
    }
    __syncthreads();   // s_w dead; cs buffers reusable

    const size_t cs_bytes = (size_t)E_N * 64 * 4;
    int* s_nxt = (int*)(sm + SM_NXT);

#define ISSUE_TILE(TI, BUF)                                                   \
    {                                                                         \
        size_t gb = (size_t)(TI) * TILE_M * 256;                              \
        uint32_t cdst = sbase + ((BUF) ? SM_CS1 : SM_CS0);                    \
        const char* csrc = (const char*)cs + gb;                              \
        _Pragma("unroll")                                                     \
        for (int i = 0; i < 8; ++i) {                                         \
            uint32_t co = (uint32_t)(i * 256 + t) * 16;                       \
            uint32_t ok = (gb + co + 16 <= cs_bytes) ? 16u : 0u;              \
            cp16(cdst + co, csrc + co, ok);                                   \
        }                                                                     \
        if (t < 128) {                                                        \
            int e = (TI) * TILE_M + t;                                        \
            cp4(sbase + ((BUF) ? SM_XS1 : SM_XS0) + t * 4, &g_xsum[e],        \
                e < E_N ? 4u : 0u);                                           \
        }                                                                     \
    }

    int ti = blockIdx.x;
    if (ti < N_TILES) ISSUE_TILE(ti, 0);
    asm volatile("cp.async.commit_group;" ::: "memory");

    const int el = t >> 1, kh = t & 1;
    int cur = 0;

    while (ti < N_TILES) {
        // ---- grab next tile from the global queue -------------------------
        if (t == 0) *s_nxt = atomicAdd(&g_tile_ctr, 1);
        __syncthreads();   // s_nxt visible; prev tile's MMA done -> bufs free
        const int nxt = *s_nxt;
        if (nxt < N_TILES) ISSUE_TILE(nxt, cur ^ 1);
        asm volatile("cp.async.commit_group;" ::: "memory");
        asm volatile("cp.async.wait_group 1;" ::: "memory");
        __syncthreads();   // cs[cur]/xs[cur] ready for all threads

        // ================= PREP: a = xs * (1/cs), fp16 hi/lo ================
        {
            const float* xsb = (const float*)(sm + (cur ? SM_XS1 : SM_XS0));
            const float4* cb = (const float4*)(sm + (cur ? SM_CS1 : SM_CS0));
            float xs = xsb[el];
            const float4* cp = cb + el * 16 + kh * 8;
            uint32_t hw[16], lw[16];
#pragma unroll
            for (int q = 0; q < 8; ++q) {
                float4 c = cp[q];
                float v0 = xs * frcp(c.x);
                float v1 = xs * frcp(c.y);
                float v2 = xs * frcp(c.z);
                float v3 = xs * frcp(c.w);
                __half h0, l0, h1, l1, h2, l2, h3, l3;
                split16(v0, h0, l0); split16(v1, h1, l1);
                split16(v2, h2, l2); split16(v3, h3, l3);
                hw[2 * q] = pack2(h0, h1); hw[2 * q + 1] = pack2(h2, h3);
                lw[2 * q] = pack2(l0, l1); lw[2 * q + 1] = pack2(l2, l3);
            }
            uint32_t off = el * A_STRIDE + kh * 64;
            uint4* dh = (uint4*)(sm + SM_A + off);
            uint4* dl = (uint4*)(sm + SM_A + A_BUF + off);
#pragma unroll
            for (int q = 0; q < 4; ++q) {
                dh[q] = make_uint4(hw[4 * q], hw[4 * q + 1], hw[4 * q + 2], hw[4 * q + 3]);
                dl[q] = make_uint4(lw[4 * q], lw[4 * q + 1], lw[4 * q + 2], lw[4 * q + 3]);
            }
        }
        __syncthreads();   // A ready

        // ================= MMA + STORE =====================================
        {
            const uint32_t ah_base = sbase + SM_A;
            const uint32_t al_base = ah_base + A_BUF;
            const int ebase = ti * TILE_M;
            const uint32_t lrow = (lane & 7) + ((lane >> 3) & 1) * 8;
            const uint32_t lcol = (lane >> 4) * 16;
            const int gr = lane >> 2;
            const int col = warp * 32 + (lane & 3) * 2;

#pragma unroll 1
            for (int m0 = 0; m0 < TILE_M; m0 += 16) {
                uint32_t fo = (m0 + lrow) * A_STRIDE + lcol;
                float acc[4][4];
#pragma unroll
                for (int nt = 0; nt < 4; ++nt)
                    acc[nt][0] = acc[nt][1] = acc[nt][2] = acc[nt][3] = 0.f;
#pragma unroll
                for (int ks = 0; ks < 4; ++ks) {
                    uint32_t ah[4], al[4];
                    ldsm4(ah, ah_base + fo + ks * 32);
                    ldsm4(al, al_base + fo + ks * 32);
#pragma unroll
                    for (int nt = 0; nt < 4; ++nt) {
                        mma16816(acc[nt], ah, bh[nt][ks][0], bh[nt][ks][1]);
                        mma16816(acc[nt], ah, bl[nt][ks][0], bl[nt][ks][1]);
                        mma16816(acc[nt], al, bh[nt][ks][0], bh[nt][ks][1]);
                    }
                }
                int e0 = ebase + m0 + gr, e1 = e0 + 8;
                if (e0 < E_N) {
                    float* p = out + (size_t)e0 * O_N + col;
#pragma unroll
                    for (int nt = 0; nt < 4; ++nt)
                        *(float2*)(p + nt * 8) = make_float2(acc[nt][0], acc[nt][1]);
                }
                if (e1 < E_N) {
                    float* p = out + (size_t)e1 * O_N + col;
#pragma unroll
                    for (int nt = 0; nt < 4; ++nt)
                        *(float2*)(p + nt * 8) = make_float2(acc[nt][2], acc[nt][3]);
                }
            }
        }
        ti = nxt;
        cur ^= 1;
    }
#undef ISSUE_TILE
}

// ---------------------------------------------------------------------------
// Inputs: x[E,256] f32, cs[E,64] f32, W[64,256,256] f32, edge_index (unused).
// Output: f32 [E,256].
// ---------------------------------------------------------------------------
extern "C" void kernel_launch(void* const* d_in, const int* in_sizes, int n_in,
                              void* d_out, int out_size) {
    const float* x  = (const float*)d_in[0];
    const float* cs = (const float*)d_in[1];
    const float* W  = (const float*)d_in[2];
    float* out = (float*)d_out;
    (void)in_sizes; (void)n_in; (void)out_size;

    int nsm = 148;
    cudaDeviceGetAttribute(&nsm, cudaDevAttrMultiProcessorCount, 0);
    const int grid = 2 * nsm;

    cudaFuncSetAttribute(rgcn_hmma_kernel,
                         cudaFuncAttributeMaxDynamicSharedMemorySize, SM_TOT);

    fused_stream_kernel<<<FUSE_BLOCKS, 256>>>(W, x);
    wsum_final_kernel<<<R_N, O_N>>>(grid);
    rgcn_hmma_kernel<<<grid, 256, SM_TOT>>>(cs, out);
}

// round 8
// speedup vs baseline: 1.0167x; 1.0167x over previous
#include <cuda_runtime.h>
#include <cuda_fp16.h>
#include <cstdint>

#define E_N 100000
#define R_N 64
#define I_N 256
#define O_N 256
#define TILE_M 128
#define N_TILES ((E_N + TILE_M - 1) / TILE_M)   // 782

#define WSUM_BLOCKS 1024
#define XSUM_BLOCKS ((E_N + 15) / 16)            // 6250, 16 rows per block
#define FUSE_BLOCKS (WSUM_BLOCKS + XSUM_BLOCKS)

// Main-kernel dynamic smem (103428 B -> 2 CTAs/SM)
#define SM_CS0   0
#define SM_CS1   32768
#define SM_XS0   65536
#define SM_XS1   66048
#define SM_A     66560
#define A_BUF    18432
#define SM_NXT   (SM_A + 2 * A_BUF)       // 4B queue-broadcast slot
#define SM_TOT   (SM_NXT + 4)
#define A_STRIDE 144                      // %128==16 -> conflict-free LDSM

__device__ float g_wpart[16 * R_N * O_N];
__device__ float g_wsum[R_N * O_N];
__device__ float g_xsum[E_N];
__device__ int   g_tile_ctr;

// ---------------------------------------------------------------------------
// Kernel 1 (fused): blocks [0,1024) -> W partial sums; rest -> x row sums
// (2 rows per warp for 4-deep load MLP).
// ---------------------------------------------------------------------------
__global__ __launch_bounds__(256, 8)
void fused_stream_kernel(const float* __restrict__ W,
                         const float* __restrict__ x) {
    const int bid = blockIdx.x;
    if (bid < WSUM_BLOCKS) {
        const int r = bid & 63;
        const int part = bid >> 6;
        const int o = threadIdx.x;
        const float* base = W + ((size_t)(r * I_N + part * 16)) * O_N + o;
        float s = 0.f;
#pragma unroll
        for (int i = 0; i < 16; ++i) s += base[(size_t)i * O_N];
        g_wpart[(part * R_N + r) * O_N + o] = s;
    } else {
        const int warp = threadIdx.x >> 5, lane = threadIdx.x & 31;
        const int row0 = (bid - WSUM_BLOCKS) * 16 + warp * 2;
        if (row0 >= E_N) return;
        const int row1 = min(row0 + 1, E_N - 1);
        const float4* xp0 = (const float4*)x + (size_t)row0 * 64;
        const float4* xp1 = (const float4*)x + (size_t)row1 * 64;
        float4 a0 = xp0[lane], a1 = xp0[lane + 32];
        float4 b0 = xp1[lane], b1 = xp1[lane + 32];
        float s0 = (a0.x + a0.y) + (a0.z + a0.w) + (a1.x + a1.y) + (a1.z + a1.w);
        float s1 = (b0.x + b0.y) + (b0.z + b0.w) + (b1.x + b1.y) + (b1.z + b1.w);
#pragma unroll
        for (int d = 16; d; d >>= 1) {
            s0 += __shfl_xor_sync(0xffffffffu, s0, d);
            s1 += __shfl_xor_sync(0xffffffffu, s1, d);
        }
        if (lane == 0) {
            g_xsum[row0] = s0;
            if (row0 + 1 < E_N) g_xsum[row0 + 1] = s1;
        }
    }
}

// ---------------------------------------------------------------------------
// Kernel 2: collapse W partials -> g_wsum; reset the tile work-queue counter.
// ---------------------------------------------------------------------------
__global__ void wsum_final_kernel(int ctr_start) {
    const int r = blockIdx.x, o = threadIdx.x;
    float s = 0.f;
#pragma unroll
    for (int p = 0; p < 16; ++p) s += g_wpart[(p * R_N + r) * O_N + o];
    g_wsum[r * O_N + o] = s;
    if (r == 0 && o == 0) g_tile_ctr = ctr_start;
}

// ---------------------------------------------------------------------------
// helpers
// ---------------------------------------------------------------------------
static __device__ __forceinline__ void mma16816(float* acc, const uint32_t* a,
                                                uint32_t b0, uint32_t b1) {
    asm volatile(
        "mma.sync.aligned.m16n8k16.row.col.f32.f16.f16.f32 "
        "{%0,%1,%2,%3}, {%4,%5,%6,%7}, {%8,%9}, {%0,%1,%2,%3};"
        : "+f"(acc[0]), "+f"(acc[1]), "+f"(acc[2]), "+f"(acc[3])
        : "r"(a[0]), "r"(a[1]), "r"(a[2]), "r"(a[3]), "r"(b0), "r"(b1));
}
static __device__ __forceinline__ void ldsm4(uint32_t* r, uint32_t saddr) {
    asm volatile("ldmatrix.sync.aligned.m8n8.x4.shared.b16 {%0,%1,%2,%3}, [%4];"
                 : "=r"(r[0]), "=r"(r[1]), "=r"(r[2]), "=r"(r[3]) : "r"(saddr));
}
static __device__ __forceinline__ uint32_t pack2(__half a, __half b) {
    __half2 h; h.x = a; h.y = b;
    return *(uint32_t*)&h;
}
static __device__ __forceinline__ void split16(float v, __half& hi, __half& lo) {
    hi = __float2half_rn(v);
    lo = __float2half_rn(v - __half2float(hi));
}
// FMA-pipe reciprocal (no MUFU): magic seed + 2 Newton iterations
static __device__ __forceinline__ float frcp(float y) {
    float r = __uint_as_float(0x7EF311C3u - __float_as_uint(y));
    r = r * __fmaf_rn(-y, r, 2.0f);
    r = r * __fmaf_rn(-y, r, 2.0f);
    return r;
}
static __device__ __forceinline__ void cp16(uint32_t dst, const void* src,
                                            uint32_t sz) {
    asm volatile("cp.async.cg.shared.global [%0], [%1], 16, %2;"
                 :: "r"(dst), "l"(src), "r"(sz) : "memory");
}
static __device__ __forceinline__ void cp4(uint32_t dst, const void* src,
                                           uint32_t sz) {
    asm volatile("cp.async.ca.shared.global [%0], [%1], 4, %2;"
                 :: "r"(dst), "l"(src), "r"(sz) : "memory");
}

// ---------------------------------------------------------------------------
// Kernel 3: persistent main kernel, 2 CTAs/SM, dynamic tile queue with the
// atomic fetch overlapped with the MMA phase (off the critical path).
// ---------------------------------------------------------------------------
__global__ __launch_bounds__(256, 2)
void rgcn_hmma_kernel(const float* __restrict__ cs,
                      float* __restrict__ out) {
    extern __shared__ __align__(16) char sm[];
    const uint32_t sbase = (uint32_t)__cvta_generic_to_shared(sm);
    const int t = threadIdx.x;
    const int warp = t >> 5, lane = t & 31;

    // ---- init: stage Wsum in smem (overlaps cs bufs), extract B frags -----
    float* s_w = (float*)sm;
#pragma unroll 4
    for (int i = 0; i < 64; ++i) {
        int idx = i * 256 + t;
        s_w[idx] = g_wsum[idx];
    }
    __syncthreads();

    uint32_t bh[4][4][2], bl[4][4][2];
    {
        const int n = warp * 32 + (lane >> 2);
#pragma unroll
        for (int nt = 0; nt < 4; ++nt)
#pragma unroll
            for (int ks = 0; ks < 4; ++ks) {
                int kb = ks * 16 + 2 * (lane & 3);
                int nn = n + nt * 8;
                float w00 = s_w[kb * 256 + nn];
                float w01 = s_w[(kb + 1) * 256 + nn];
                float w10 = s_w[(kb + 8) * 256 + nn];
                float w11 = s_w[(kb + 9) * 256 + nn];
                __half h00, l00, h01, l01, h10, l10, h11, l11;
                split16(w00, h00, l00); split16(w01, h01, l01);
                split16(w10, h10, l10); split16(w11, h11, l11);
                bh[nt][ks][0] = pack2(h00, h01); bh[nt][ks][1] = pack2(h10, h11);
                bl[nt][ks][0] = pack2(l00, l01); bl[nt][ks][1] = pack2(l10, l11);
            }
    }
    __syncthreads();   // s_w dead; cs buffers reusable

    const size_t cs_bytes = (size_t)E_N * 64 * 4;
    volatile int* s_nxt = (volatile int*)(sm + SM_NXT);

#define ISSUE_TILE(TI, BUF)                                                   \
    {                                                                         \
        size_t gb = (size_t)(TI) * TILE_M * 256;                              \
        uint32_t cdst = sbase + ((BUF) ? SM_CS1 : SM_CS0);                    \
        const char* csrc = (const char*)cs + gb;                              \
        _Pragma("unroll")                                                     \
        for (int i = 0; i < 8; ++i) {                                         \
            uint32_t co = (uint32_t)(i * 256 + t) * 16;                       \
            uint32_t ok = (gb + co + 16 <= cs_bytes) ? 16u : 0u;              \
            cp16(cdst + co, csrc + co, ok);                                   \
        }                                                                     \
        if (t < 128) {                                                        \
            int e = (TI) * TILE_M + t;                                        \
            cp4(sbase + ((BUF) ? SM_XS1 : SM_XS0) + t * 4, &g_xsum[e],        \
                e < E_N ? 4u : 0u);                                           \
        }                                                                     \
    }

    // prologue: current tile = blockIdx, prefetch it, and fetch the first
    // "next" tile index from the queue.
    int ti = blockIdx.x;
    if (ti < N_TILES) ISSUE_TILE(ti, 0);
    asm volatile("cp.async.commit_group;" ::: "memory");
    if (t == 0) *s_nxt = atomicAdd(&g_tile_ctr, 1);
    __syncthreads();
    int nxt = *s_nxt;

    const int el = t >> 1, kh = t & 1;
    int cur = 0;

    while (ti < N_TILES) {
        // issue next tile's prefetch (index known since last iteration)
        if (nxt < N_TILES) ISSUE_TILE(nxt, cur ^ 1);
        asm volatile("cp.async.commit_group;" ::: "memory");
        asm volatile("cp.async.wait_group 1;" ::: "memory");
        __syncthreads();   // cs[cur]/xs[cur] ready; prev MMA done -> A free

        // ================= PREP: a = xs * (1/cs), fp16 hi/lo ================
        {
            const float* xsb = (const float*)(sm + (cur ? SM_XS1 : SM_XS0));
            const float4* cb = (const float4*)(sm + (cur ? SM_CS1 : SM_CS0));
            float xs = xsb[el];
            const float4* cp = cb + el * 16 + kh * 8;
            uint32_t hw[16], lw[16];
#pragma unroll
            for (int q = 0; q < 8; ++q) {
                float4 c = cp[q];
                float v0 = xs * frcp(c.x);
                float v1 = xs * frcp(c.y);
                float v2 = xs * frcp(c.z);
                float v3 = xs * frcp(c.w);
                __half h0, l0, h1, l1, h2, l2, h3, l3;
                split16(v0, h0, l0); split16(v1, h1, l1);
                split16(v2, h2, l2); split16(v3, h3, l3);
                hw[2 * q] = pack2(h0, h1); hw[2 * q + 1] = pack2(h2, h3);
                lw[2 * q] = pack2(l0, l1); lw[2 * q + 1] = pack2(l2, l3);
            }
            uint32_t off = el * A_STRIDE + kh * 64;
            uint4* dh = (uint4*)(sm + SM_A + off);
            uint4* dl = (uint4*)(sm + SM_A + A_BUF + off);
#pragma unroll
            for (int q = 0; q < 4; ++q) {
                dh[q] = make_uint4(hw[4 * q], hw[4 * q + 1], hw[4 * q + 2], hw[4 * q + 3]);
                dl[q] = make_uint4(lw[4 * q], lw[4 * q + 1], lw[4 * q + 2], lw[4 * q + 3]);
            }
        }
        __syncthreads();   // A ready

        // fetch tile t+2 from the queue; latency hidden under the MMA phase,
        // published by the post-MMA barrier.
        if (t == 0) *s_nxt = atomicAdd(&g_tile_ctr, 1);

        // ================= MMA + STORE =====================================
        {
            const uint32_t ah_base = sbase + SM_A;
            const uint32_t al_base = ah_base + A_BUF;
            const int ebase = ti * TILE_M;
            const uint32_t lrow = (lane & 7) + ((lane >> 3) & 1) * 8;
            const uint32_t lcol = (lane >> 4) * 16;
            const int gr = lane >> 2;
            const int col = warp * 32 + (lane & 3) * 2;

#pragma unroll 1
            for (int m0 = 0; m0 < TILE_M; m0 += 16) {
                uint32_t fo = (m0 + lrow) * A_STRIDE + lcol;
                float acc[4][4];
#pragma unroll
                for (int nt = 0; nt < 4; ++nt)
                    acc[nt][0] = acc[nt][1] = acc[nt][2] = acc[nt][3] = 0.f;
#pragma unroll
                for (int ks = 0; ks < 4; ++ks) {
                    uint32_t ah[4], al[4];
                    ldsm4(ah, ah_base + fo + ks * 32);
                    ldsm4(al, al_base + fo + ks * 32);
#pragma unroll
                    for (int nt = 0; nt < 4; ++nt) {
                        mma16816(acc[nt], ah, bh[nt][ks][0], bh[nt][ks][1]);
                        mma16816(acc[nt], ah, bl[nt][ks][0], bl[nt][ks][1]);
                        mma16816(acc[nt], al, bh[nt][ks][0], bh[nt][ks][1]);
                    }
                }
                int e0 = ebase + m0 + gr, e1 = e0 + 8;
                if (e0 < E_N) {
                    float* p = out + (size_t)e0 * O_N + col;
#pragma unroll
                    for (int nt = 0; nt < 4; ++nt)
                        *(float2*)(p + nt * 8) = make_float2(acc[nt][0], acc[nt][1]);
                }
                if (e1 < E_N) {
                    float* p = out + (size_t)e1 * O_N + col;
#pragma unroll
                    for (int nt = 0; nt < 4; ++nt)
                        *(float2*)(p + nt * 8) = make_float2(acc[nt][2], acc[nt][3]);
                }
            }
        }
        __syncthreads();   // MMA done (A free), s_nxt visible to all
        ti = nxt;
        nxt = *s_nxt;
        cur ^= 1;
    }
#undef ISSUE_TILE
}

// ---------------------------------------------------------------------------
// Inputs: x[E,256] f32, cs[E,64] f32, W[64,256,256] f32, edge_index (unused).
// Output: f32 [E,256].
// ---------------------------------------------------------------------------
extern "C" void kernel_launch(void* const* d_in, const int* in_sizes, int n_in,
                              void* d_out, int out_size) {
    const float* x  = (const float*)d_in[0];
    const float* cs = (const float*)d_in[1];
    const float* W  = (const float*)d_in[2];
    float* out = (float*)d_out;
    (void)in_sizes; (void)n_in; (void)out_size;

    int nsm = 148;
    cudaDeviceGetAttribute(&nsm, cudaDevAttrMultiProcessorCount, 0);
    const int grid = 2 * nsm;

    cudaFuncSetAttribute(rgcn_hmma_kernel,
                         cudaFuncAttributeMaxDynamicSharedMemorySize, SM_TOT);

    fused_stream_kernel<<<FUSE_BLOCKS, 256>>>(W, x);
    wsum_final_kernel<<<R_N, O_N>>>(grid);
    rgcn_hmma_kernel<<<grid, 256, SM_TOT>>>(cs, out);
}